// round 1
// baseline (speedup 1.0000x reference)
#include <cuda_runtime.h>

// TransPooling: out[b,c,n] = pts[b,c,n] * diag_softmax[b,n]
// where diag_softmax[b,n] = softmax_m( x_n^T (Wq^T Wk) x_m )[m=n]
//
// Decomposition:
//   A[d][c] = log2(e) * sum_e Wq[e][c] * Wk[e][d]        (= log2e * (Wq^T Wk)^T)
//   Z[b][d][n] = sum_c A[d][c] * X[b][c][n]              (logits in log2 domain)
//   l'[b][n][m] = sum_c Z[b][c][n] * X[b][c][m]
//   diag[b][n] = 2^(l'nn - max_m) / sum_m 2^(l'nm - max_m)   (streamed, never stored)

#define CC 256
#define NN 4096
#define BB 8

static __device__ float g_A[CC * CC];
static __device__ float g_Z[(size_t)BB * CC * NN];

__device__ __forceinline__ float fexp2(float x) {
    float y;
    asm("ex2.approx.ftz.f32 %0, %1;" : "=f"(y) : "f"(x));
    return y;
}

// ---------------------------------------------------------------------------
// A[d][c] = log2e * sum_e Wq[e][c] * Wk[e][d]
// ---------------------------------------------------------------------------
__global__ void k_prepA(const float* __restrict__ Wq, const float* __restrict__ Wk) {
    const float LOG2E = 1.4426950408889634f;
    int c = blockIdx.x * 32 + threadIdx.x;
    int d = blockIdx.y * 8 + threadIdx.y;
    float s = 0.f;
#pragma unroll 8
    for (int e = 0; e < CC; e++)
        s = fmaf(Wq[e * CC + c], Wk[e * CC + d], s);
    g_A[d * CC + c] = s * LOG2E;
}

// ---------------------------------------------------------------------------
// Z[b][d][n] = sum_c A[d][c] * X[b][c][n]
// grid (N/128, C/128, B), 256 threads, 128x128 tile, 8x8 microtile
// ---------------------------------------------------------------------------
__global__ __launch_bounds__(256) void k_Z(const float* __restrict__ X) {
    __shared__ float As[16 * 132];  // [c_local][d_local], padded rows (16B-aligned)
    __shared__ float Xs[16 * 128];  // [c_local][n_local]
    const int tid = threadIdx.x;
    const int tx = tid & 15, ty = tid >> 4;
    const int b = blockIdx.z;
    const int d0 = blockIdx.y << 7;
    const int n0 = blockIdx.x << 7;
    const float* Xb = X + (size_t)b * CC * NN;

    float acc[8][8];
#pragma unroll
    for (int i = 0; i < 8; i++)
#pragma unroll
        for (int j = 0; j < 8; j++) acc[i][j] = 0.f;

#pragma unroll 1
    for (int kc = 0; kc < CC; kc += 16) {
        __syncthreads();
        // A tile [128 d x 16 c], stored transposed into As[c][d]
#pragma unroll
        for (int t = 0; t < 2; t++) {
            int f = tid * 2 + t;          // 0..511 float4s
            int row = f >> 2;             // d_local 0..127
            int c4 = (f & 3) << 2;        // c_local 0,4,8,12
            float4 v = *(const float4*)&g_A[(d0 + row) * CC + kc + c4];
            As[(c4 + 0) * 132 + row] = v.x;
            As[(c4 + 1) * 132 + row] = v.y;
            As[(c4 + 2) * 132 + row] = v.z;
            As[(c4 + 3) * 132 + row] = v.w;
        }
        // X tile [16 c x 128 n]
#pragma unroll
        for (int t = 0; t < 2; t++) {
            int f = tid + t * 256;        // 0..511 float4s
            int row = f >> 5;             // c_local 0..15
            int c4 = (f & 31) << 2;       // n_local
            *(float4*)&Xs[row * 128 + c4] =
                *(const float4*)&Xb[(size_t)(kc + row) * NN + n0 + c4];
        }
        __syncthreads();
#pragma unroll
        for (int k = 0; k < 16; k++) {
            float4 a0 = *(const float4*)&As[k * 132 + ty * 8];
            float4 a1 = *(const float4*)&As[k * 132 + ty * 8 + 4];
            float4 b0 = *(const float4*)&Xs[k * 128 + tx * 8];
            float4 b1 = *(const float4*)&Xs[k * 128 + tx * 8 + 4];
            float a[8] = {a0.x, a0.y, a0.z, a0.w, a1.x, a1.y, a1.z, a1.w};
            float bv[8] = {b0.x, b0.y, b0.z, b0.w, b1.x, b1.y, b1.z, b1.w};
#pragma unroll
            for (int i = 0; i < 8; i++)
#pragma unroll
                for (int j = 0; j < 8; j++)
                    acc[i][j] = fmaf(a[i], bv[j], acc[i][j]);
        }
    }

    float* Zb = g_Z + (size_t)b * CC * NN;
#pragma unroll
    for (int i = 0; i < 8; i++) {
        float4 v0 = make_float4(acc[i][0], acc[i][1], acc[i][2], acc[i][3]);
        float4 v1 = make_float4(acc[i][4], acc[i][5], acc[i][6], acc[i][7]);
        size_t off = (size_t)(d0 + ty * 8 + i) * NN + n0 + tx * 8;
        *(float4*)&Zb[off] = v0;
        *(float4*)&Zb[off + 4] = v1;
    }
}

// ---------------------------------------------------------------------------
// Main: per CTA = 128 rows (n) of one batch. Stream m-tiles of 128 columns,
// tile-GEMM 128x128x256 (fp32), online softmax reduction (max / sum / diag),
// then write out = X * diag for the owned rows.
// grid (B*32), 256 threads.
// ---------------------------------------------------------------------------
__global__ __launch_bounds__(256) void k_main(const float* __restrict__ X,
                                              float* __restrict__ out) {
    __shared__ float Zs[16 * 128];   // [c_local][n_local]  (rows of this CTA)
    __shared__ float Xs[16 * 128];   // [c_local][m_local]  (streamed columns)
    __shared__ float sdiag[128];
    const int tid = threadIdx.x;
    const int tx = tid & 15, ty = tid >> 4;
    const int b = blockIdx.x >> 5;
    const int nt = blockIdx.x & 31;
    const int n0 = nt << 7;
    const float* Xb = X + (size_t)b * CC * NN;
    const float* Zb = g_Z + (size_t)b * CC * NN;

    float mrun[8], rsum[8], dlog[8];
#pragma unroll
    for (int i = 0; i < 8; i++) {
        mrun[i] = -3.0e38f;
        rsum[i] = 0.f;
        dlog[i] = 0.f;
    }

#pragma unroll 1
    for (int mt = 0; mt < 32; ++mt) {
        const int m0 = mt << 7;
        float acc[8][8];
#pragma unroll
        for (int i = 0; i < 8; i++)
#pragma unroll
            for (int j = 0; j < 8; j++) acc[i][j] = 0.f;

#pragma unroll 1
        for (int kc = 0; kc < CC; kc += 16) {
            __syncthreads();
#pragma unroll
            for (int t = 0; t < 2; t++) {
                int f = tid + t * 256;
                int row = f >> 5;
                int c4 = (f & 31) << 2;
                *(float4*)&Zs[row * 128 + c4] =
                    *(const float4*)&Zb[(size_t)(kc + row) * NN + n0 + c4];
                *(float4*)&Xs[row * 128 + c4] =
                    *(const float4*)&Xb[(size_t)(kc + row) * NN + m0 + c4];
            }
            __syncthreads();
#pragma unroll
            for (int k = 0; k < 16; k++) {
                float4 a0 = *(const float4*)&Zs[k * 128 + ty * 8];
                float4 a1 = *(const float4*)&Zs[k * 128 + ty * 8 + 4];
                float4 b0 = *(const float4*)&Xs[k * 128 + tx * 8];
                float4 b1 = *(const float4*)&Xs[k * 128 + tx * 8 + 4];
                float a[8] = {a0.x, a0.y, a0.z, a0.w, a1.x, a1.y, a1.z, a1.w};
                float bv[8] = {b0.x, b0.y, b0.z, b0.w, b1.x, b1.y, b1.z, b1.w};
#pragma unroll
                for (int i = 0; i < 8; i++)
#pragma unroll
                    for (int j = 0; j < 8; j++)
                        acc[i][j] = fmaf(a[i], bv[j], acc[i][j]);
            }
        }

        // ---- online softmax epilogue for this 128-column tile ----
        // diagonal tile: row n0+ty*8+i == col m0+tx*8+j  <=>  mt==nt, tx==ty, j==i
        if (mt == nt && tx == ty) {
#pragma unroll
            for (int i = 0; i < 8; i++) dlog[i] = acc[i][i];
        }
#pragma unroll
        for (int i = 0; i < 8; i++) {
            float tm = acc[i][0];
#pragma unroll
            for (int j = 1; j < 8; j++) tm = fmaxf(tm, acc[i][j]);
            // reduce over the 16 tx-threads (lane bits 0..3)
#pragma unroll
            for (int s = 1; s < 16; s <<= 1)
                tm = fmaxf(tm, __shfl_xor_sync(0xffffffffu, tm, s));
            float mn = fmaxf(mrun[i], tm);
            float ps = 0.f;
#pragma unroll
            for (int j = 0; j < 8; j++) ps += fexp2(acc[i][j] - mn);
#pragma unroll
            for (int s = 1; s < 16; s <<= 1)
                ps += __shfl_xor_sync(0xffffffffu, ps, s);
            rsum[i] = rsum[i] * fexp2(mrun[i] - mn) + ps;
            mrun[i] = mn;
        }
    }

    if (tx == ty) {
#pragma unroll
        for (int i = 0; i < 8; i++)
            sdiag[ty * 8 + i] =
                fexp2(dlog[i] - mrun[i]) / rsum[i] * (1.0f / (1.0f + 1e-8f));
    }
    __syncthreads();

    // out[b][c][n0..n0+127] = X * diag   (256 rows x 128 cols = 8192 float4s)
    float* Ob = out + (size_t)b * CC * NN;
#pragma unroll 4
    for (int t = 0; t < 32; t++) {
        int f = tid + t * 256;
        int row = f >> 5;           // c 0..255
        int c4 = (f & 31) << 2;     // n_local
        float4 v = *(const float4*)&Xb[(size_t)row * NN + n0 + c4];
        float4 dv = *(const float4*)&sdiag[c4];
        v.x *= dv.x;
        v.y *= dv.y;
        v.z *= dv.z;
        v.w *= dv.w;
        *(float4*)&Ob[(size_t)row * NN + n0 + c4] = v;
    }
}

// ---------------------------------------------------------------------------
extern "C" void kernel_launch(void* const* d_in, const int* in_sizes, int n_in,
                              void* d_out, int out_size) {
    const float* X  = (const float*)d_in[0];   // pts_feat [B, C, N]
    const float* Wq = (const float*)d_in[1];   // [C, C]
    const float* Wk = (const float*)d_in[2];   // [C, C]
    float* out = (float*)d_out;                // [B, C, N]

    k_prepA<<<dim3(8, 32), dim3(32, 8)>>>(Wq, Wk);
    k_Z<<<dim3(NN / 128, CC / 128, BB), 256>>>(X);
    k_main<<<dim3(BB * (NN / 128)), 256>>>(X, out);
}

// round 3
// speedup vs baseline: 1.2381x; 1.2381x over previous
#include <cuda_runtime.h>
#include <cuda_bf16.h>
#include <cstdint>

#define CC 256
#define NN 4096
#define BB 8

// ---------------- device globals (no runtime allocs allowed) ----------------
static __device__ __nv_bfloat16 g_Ah[CC * CC];      // A hi  [d][c]
static __device__ __nv_bfloat16 g_Al[CC * CC];      // A lo
static __device__ __nv_bfloat16 g_Xt_hi[(size_t)BB * NN * CC];  // X^T hi [b][n][c]
static __device__ __nv_bfloat16 g_Xt_lo[(size_t)BB * NN * CC];
static __device__ __nv_bfloat16 g_Zt_hi[(size_t)BB * NN * CC];  // Z^T hi [b][n][d]
static __device__ __nv_bfloat16 g_Zt_lo[(size_t)BB * NN * CC];

// ---------------- helpers ----------------
__device__ __forceinline__ float fexp2(float x) {
    float y;
    asm("ex2.approx.ftz.f32 %0, %1;" : "=f"(y) : "f"(x));
    return y;
}
__device__ __forceinline__ uint32_t smem_u32(const void* p) {
    uint32_t a;
    asm("{ .reg .u64 t; cvta.to.shared.u64 t, %1; cvt.u32.u64 %0, t; }" : "=r"(a) : "l"(p));
    return a;
}
#define SWZ(o) ((o) ^ (((o) >> 3) & 0x70))

#define CP16(dst, src) \
    asm volatile("cp.async.cg.shared.global [%0], [%1], 16;" :: "r"(dst), "l"(src) : "memory")
#define CP_COMMIT() asm volatile("cp.async.commit_group;" ::: "memory")
#define CP_WAIT0()  asm volatile("cp.async.wait_group 0;" ::: "memory")

__device__ __forceinline__ void ldsm4(uint32_t* r, uint32_t a) {
    asm volatile("ldmatrix.sync.aligned.m8n8.x4.shared.b16 {%0,%1,%2,%3}, [%4];"
        : "=r"(r[0]), "=r"(r[1]), "=r"(r[2]), "=r"(r[3]) : "r"(a));
}
__device__ __forceinline__ void mma16816(float* d, const uint32_t* a, const uint32_t* b) {
    asm volatile("mma.sync.aligned.m16n8k16.row.col.f32.bf16.bf16.f32 "
        "{%0,%1,%2,%3}, {%4,%5,%6,%7}, {%8,%9}, {%0,%1,%2,%3};"
        : "+f"(d[0]), "+f"(d[1]), "+f"(d[2]), "+f"(d[3])
        : "r"(a[0]), "r"(a[1]), "r"(a[2]), "r"(a[3]), "r"(b[0]), "r"(b[1]));
}
__device__ __forceinline__ uint32_t pack_bf16x2(__nv_bfloat16 a, __nv_bfloat16 b) {
    return (uint32_t)__bfloat16_as_ushort(a) | ((uint32_t)__bfloat16_as_ushort(b) << 16);
}

// ---------------------------------------------------------------------------
// A[d][c] = log2e * sum_e Wq[e][c] * Wk[e][d], stored as bf16 hi/lo
// ---------------------------------------------------------------------------
__global__ void k_prepA(const float* __restrict__ Wq, const float* __restrict__ Wk) {
    const float LOG2E = 1.4426950408889634f;
    int c = blockIdx.x * 32 + threadIdx.x;
    int d = blockIdx.y * 8 + threadIdx.y;
    float s0 = 0.f, s1 = 0.f;
#pragma unroll 8
    for (int e = 0; e < CC; e += 2) {
        s0 = fmaf(Wq[e * CC + c], Wk[e * CC + d], s0);
        s1 = fmaf(Wq[(e + 1) * CC + c], Wk[(e + 1) * CC + d], s1);
    }
    float v = (s0 + s1) * LOG2E;
    __nv_bfloat16 h = __float2bfloat16(v);
    g_Ah[d * CC + c] = h;
    g_Al[d * CC + c] = __float2bfloat16(v - __bfloat162float(h));
}

// ---------------------------------------------------------------------------
// Transpose + bf16 hi/lo split: X[b][c][n] -> Xt_hi/lo[b][n][c]
// ---------------------------------------------------------------------------
__global__ __launch_bounds__(256) void k_prep(const float* __restrict__ X) {
    __shared__ float s[32][33];
    const int b = blockIdx.z, c0 = blockIdx.y * 32, n0 = blockIdx.x * 32;
    const int tx = threadIdx.x, ty = threadIdx.y;
    const float* Xb = X + (size_t)b * CC * NN;
#pragma unroll
    for (int i = 0; i < 4; i++)
        s[ty + 8 * i][tx] = Xb[(size_t)(c0 + ty + 8 * i) * NN + n0 + tx];
    __syncthreads();
    const size_t base = (size_t)b * NN * CC;
#pragma unroll
    for (int i = 0; i < 4; i++) {
        int n = n0 + ty + 8 * i;
        float v = s[tx][ty + 8 * i];
        __nv_bfloat16 h = __float2bfloat16(v);
        g_Xt_hi[base + (size_t)n * CC + c0 + tx] = h;
        g_Xt_lo[base + (size_t)n * CC + c0 + tx] =
            __float2bfloat16(v - __bfloat162float(h));
    }
}

// ---------------------------------------------------------------------------
// k_Zt: Zt[n][d] = sum_c Xt[n][c] * A[d][c]   (3-term bf16 split, mma.sync)
// grid (32 nt, 2 dt, 8 b), 256 threads (8 warps x 16 rows x 128 cols)
// SMEM: 2 buffers x 4 tiles (Xh, Xl, Ah, Al) x 16KB = 128KB
// ---------------------------------------------------------------------------
__global__ __launch_bounds__(256, 1) void k_Zt() {
    extern __shared__ char smem[];
    const uint32_t sb = smem_u32(smem);
    const int tid = threadIdx.x;
    const int wid = tid >> 5, lane = tid & 31;
    const int g = lane >> 2;
    const int n0 = blockIdx.x << 7;
    const int d0 = blockIdx.y << 7;
    const int b = blockIdx.z;
    const size_t bbase = (size_t)b * NN * CC;
    const char* Xsrc[2] = {(const char*)(g_Xt_hi + bbase), (const char*)(g_Xt_lo + bbase)};
    const char* Asrc[2] = {(const char*)g_Ah, (const char*)g_Al};

    // lane constants
    const int aRow = wid * 16 + (lane & 15);             // row in A-operand (Xt)
    const uint32_t aOff = (uint32_t)(aRow * 128);
    const uint32_t aSwz = (uint32_t)((aRow * 16) & 0x70);
    const int aColX = (lane >> 4) << 4;
    const int bRowOff = (lane & 7) + ((lane >> 4) & 1) * 8;
    const int bColX = ((lane >> 3) & 1) << 4;

    float acc[16][4];
#pragma unroll
    for (int i = 0; i < 16; i++)
#pragma unroll
        for (int j = 0; j < 4; j++) acc[i][j] = 0.f;

    // prologue: load chunk 0 (X tiles rows n0.., A tiles rows d0..)
#pragma unroll
    for (int t = 0; t < 16; t++) {
        int o = tid + t * 256;
        int role = o >> 10, r = (o >> 3) & 127, j = o & 7;
        const char* src = (role < 2)
            ? Xsrc[role] + ((size_t)(n0 + r) * CC) * 2 + j * 16
            : Asrc[role - 2] + ((size_t)(d0 + r) * CC) * 2 + j * 16;
        uint32_t dst = sb + (uint32_t)role * 16384u + SWZ((uint32_t)(r * 128 + j * 16));
        CP16(dst, src);
    }
    CP_COMMIT();

#pragma unroll 1
    for (int cc = 0; cc < 4; cc++) {
        const int buf = cc & 1;
        CP_WAIT0();
        __syncthreads();
        if (cc < 3) {
            const int cn = cc + 1, bn = buf ^ 1;
#pragma unroll
            for (int t = 0; t < 16; t++) {
                int o = tid + t * 256;
                int role = o >> 10, r = (o >> 3) & 127, j = o & 7;
                const char* src = (role < 2)
                    ? Xsrc[role] + ((size_t)(n0 + r) * CC + cn * 64) * 2 + j * 16
                    : Asrc[role - 2] + ((size_t)(d0 + r) * CC + cn * 64) * 2 + j * 16;
                uint32_t dst = sb + (uint32_t)(bn * 4 + role) * 16384u +
                               SWZ((uint32_t)(r * 128 + j * 16));
                CP16(dst, src);
            }
        }
        CP_COMMIT();

        const uint32_t xh = sb + (uint32_t)(buf * 4 + 0) * 16384u;
        const uint32_t xl = xh + 16384u;
        const uint32_t ah = sb + (uint32_t)(buf * 4 + 2) * 16384u;
        const uint32_t al = ah + 16384u;
#pragma unroll
        for (int ks = 0; ks < 4; ks++) {
            const int cb = ks * 32;
            uint32_t Ah[4], Al[4];
            uint32_t aoff = aOff + (uint32_t)((cb + aColX) ^ aSwz);
            ldsm4(Ah, xh + aoff);
            ldsm4(Al, xl + aoff);
#pragma unroll
            for (int j2 = 0; j2 < 8; j2++) {
                uint32_t Bh[4], Bl[4];
                int brow = j2 * 16 + bRowOff;
                uint32_t boff = (uint32_t)(brow * 128) +
                                (uint32_t)((cb + bColX) ^ ((brow * 16) & 0x70));
                ldsm4(Bh, ah + boff);
                ldsm4(Bl, al + boff);
                mma16816(acc[j2 * 2],     Ah, Bh);
                mma16816(acc[j2 * 2 + 1], Ah, Bh + 2);
                mma16816(acc[j2 * 2],     Ah, Bl);
                mma16816(acc[j2 * 2 + 1], Ah, Bl + 2);
                mma16816(acc[j2 * 2],     Al, Bh);
                mma16816(acc[j2 * 2 + 1], Al, Bh + 2);
            }
        }
    }

    // store Zt hi/lo: rows n0 + wid*16 + h*8 + g, cols d0 + bt*8 + 2c + e
    char* Zh = (char*)(g_Zt_hi + bbase);
    char* Zl = (char*)(g_Zt_lo + bbase);
#pragma unroll
    for (int h = 0; h < 2; h++) {
        int n = n0 + wid * 16 + h * 8 + g;
#pragma unroll
        for (int bt = 0; bt < 16; bt++) {
            float v0 = acc[bt][2 * h], v1 = acc[bt][2 * h + 1];
            __nv_bfloat16 h0 = __float2bfloat16(v0);
            __nv_bfloat16 h1 = __float2bfloat16(v1);
            __nv_bfloat16 l0 = __float2bfloat16(v0 - __bfloat162float(h0));
            __nv_bfloat16 l1 = __float2bfloat16(v1 - __bfloat162float(h1));
            size_t off = ((size_t)n * CC + d0 + bt * 8 + 2 * (lane & 3)) * 2;
            *(uint32_t*)(Zh + off) = pack_bf16x2(h0, h1);
            *(uint32_t*)(Zl + off) = pack_bf16x2(l0, l1);
        }
    }
}

// ---------------------------------------------------------------------------
// k_main: S[n][m] = sum_d Zt[n][d] * Xt[m][d]  (3-term bf16 split, mma.sync),
// online softmax diag, out = X * diag.
// grid (B*32) CTAs, 256 threads (8 warps x 16 rows x 128 cols).
// SMEM: Z persistent 8 tiles (cc x {hi,lo}) 128KB + X 2buf x {hi,lo} 64KB + diag
// ---------------------------------------------------------------------------
#define SM_ZS 0u
#define SM_XS 131072u
#define SM_DIAG 196608u
#define SM_TOTAL (196608 + 512)

__global__ __launch_bounds__(256, 1) void k_main(const float* __restrict__ X,
                                                 float* __restrict__ out) {
    extern __shared__ char smem[];
    const uint32_t sb = smem_u32(smem);
    const int tid = threadIdx.x;
    const int wid = tid >> 5, lane = tid & 31;
    const int g = lane >> 2;
    const int b = blockIdx.x >> 5;
    const int nt = blockIdx.x & 31;
    const int n0 = nt << 7;
    const size_t bbase = (size_t)b * NN * CC;
    const char* Zsrc[2] = {(const char*)(g_Zt_hi + bbase), (const char*)(g_Zt_lo + bbase)};
    const char* Xsrc[2] = {(const char*)(g_Xt_hi + bbase), (const char*)(g_Xt_lo + bbase)};

    // lane constants
    const int aRow = wid * 16 + (lane & 15);
    const uint32_t aOff = (uint32_t)(aRow * 128);
    const uint32_t aSwz = (uint32_t)((aRow * 16) & 0x70);
    const int aColX = (lane >> 4) << 4;
    const int bRowOff = (lane & 7) + ((lane >> 4) & 1) * 8;
    const int bColX = ((lane >> 3) & 1) << 4;

    // prologue: persistent Z (8 tiles: cc x {hi,lo}) + X chunk 0 into buf 0
#pragma unroll 4
    for (int t = 0; t < 32; t++) {
        int o = tid + t * 256;
        int ch = o >> 11, hs = (o >> 10) & 1, r = (o >> 3) & 127, j = o & 7;
        const char* src = Zsrc[hs] + ((size_t)(n0 + r) * CC + ch * 64) * 2 + j * 16;
        uint32_t dst = sb + SM_ZS + (uint32_t)(ch * 2 + hs) * 16384u +
                       SWZ((uint32_t)(r * 128 + j * 16));
        CP16(dst, src);
    }
#pragma unroll
    for (int t = 0; t < 8; t++) {
        int o = tid + t * 256;
        int hs = o >> 10, r = (o >> 3) & 127, j = o & 7;
        const char* src = Xsrc[hs] + ((size_t)r * CC) * 2 + j * 16;
        uint32_t dst = sb + SM_XS + (uint32_t)hs * 16384u + SWZ((uint32_t)(r * 128 + j * 16));
        CP16(dst, src);
    }
    CP_COMMIT();

    float acc[16][4];
#pragma unroll
    for (int i = 0; i < 16; i++)
#pragma unroll
        for (int j = 0; j < 4; j++) acc[i][j] = 0.f;
    float mrun[2] = {-3.0e38f, -3.0e38f};
    float rsum[2] = {0.f, 0.f};
    float dlog[2] = {0.f, 0.f};
    float* sdiag = (float*)(smem + SM_DIAG);

#pragma unroll 1
    for (int G = 0; G < 128; G++) {
        const int cc = G & 3, mt = G >> 2, buf = G & 1;
        CP_WAIT0();
        __syncthreads();

        // prefetch chunk G+1 into buf^1 (its previous contents, chunk G-1,
        // were consumed before the __syncthreads above)
        if (G < 127) {
            const int Gn = G + 1;
            const int ccn = Gn & 3, m0n = (Gn >> 2) << 7, bn = buf ^ 1;
#pragma unroll
            for (int t = 0; t < 8; t++) {
                int o = tid + t * 256;
                int hs = o >> 10, r = (o >> 3) & 127, j = o & 7;
                const char* src = Xsrc[hs] + ((size_t)(m0n + r) * CC + ccn * 64) * 2 + j * 16;
                uint32_t dst = sb + SM_XS + (uint32_t)(bn * 2 + hs) * 16384u +
                               SWZ((uint32_t)(r * 128 + j * 16));
                CP16(dst, src);
            }
        }
        CP_COMMIT();

        const uint32_t zh = sb + SM_ZS + (uint32_t)(cc * 2) * 16384u;
        const uint32_t zl = zh + 16384u;
        const uint32_t xh = sb + SM_XS + (uint32_t)(buf * 2) * 16384u;
        const uint32_t xl = xh + 16384u;
#pragma unroll
        for (int ks = 0; ks < 4; ks++) {
            const int cb = ks * 32;
            uint32_t Ah[4], Al[4];
            uint32_t aoff = aOff + (uint32_t)((cb + aColX) ^ aSwz);
            ldsm4(Ah, zh + aoff);
            ldsm4(Al, zl + aoff);
#pragma unroll
            for (int j2 = 0; j2 < 8; j2++) {
                uint32_t Bh[4], Bl[4];
                int brow = j2 * 16 + bRowOff;
                uint32_t boff = (uint32_t)(brow * 128) +
                                (uint32_t)((cb + bColX) ^ ((brow * 16) & 0x70));
                ldsm4(Bh, xh + boff);
                ldsm4(Bl, xl + boff);
                mma16816(acc[j2 * 2],     Ah, Bh);
                mma16816(acc[j2 * 2 + 1], Ah, Bh + 2);
                mma16816(acc[j2 * 2],     Ah, Bl);
                mma16816(acc[j2 * 2 + 1], Ah, Bl + 2);
                mma16816(acc[j2 * 2],     Al, Bh);
                mma16816(acc[j2 * 2 + 1], Al, Bh + 2);
            }
        }

        // ---- tile boundary: online softmax on register accumulators ----
        if (cc == 3) {
#pragma unroll
            for (int h = 0; h < 2; h++) {
                float tm = -3.0e38f;
#pragma unroll
                for (int bt = 0; bt < 16; bt++)
                    tm = fmaxf(tm, fmaxf(acc[bt][2 * h], acc[bt][2 * h + 1]));
                tm = fmaxf(tm, __shfl_xor_sync(0xffffffffu, tm, 1));
                tm = fmaxf(tm, __shfl_xor_sync(0xffffffffu, tm, 2));
                float mn = fmaxf(mrun[h], tm);
                float ps = 0.f;
#pragma unroll
                for (int bt = 0; bt < 16; bt++) {
                    ps += fexp2(acc[bt][2 * h] - mn);
                    ps += fexp2(acc[bt][2 * h + 1] - mn);
                }
                ps += __shfl_xor_sync(0xffffffffu, ps, 1);
                ps += __shfl_xor_sync(0xffffffffu, ps, 2);
                rsum[h] = rsum[h] * fexp2(mrun[h] - mn) + ps;
                mrun[h] = mn;
                if (mt == nt) {
                    int rl = wid * 16 + h * 8 + g;           // row-local = diag col
                    int bt = rl >> 3;
                    if ((lane & 3) == ((rl & 7) >> 1))
                        dlog[h] = acc[bt][2 * h + (rl & 1)];
                }
            }
#pragma unroll
            for (int i = 0; i < 16; i++)
#pragma unroll
                for (int j = 0; j < 4; j++) acc[i][j] = 0.f;
        }
    }

    // write diag (one lane per row holds dlog)
#pragma unroll
    for (int h = 0; h < 2; h++) {
        int rl = wid * 16 + h * 8 + g;
        if ((lane & 3) == ((rl & 7) >> 1))
            sdiag[rl] = fexp2(dlog[h] - mrun[h]) / rsum[h] * (1.0f / (1.0f + 1e-8f));
    }
    __syncthreads();

    // out[b][c][n0..n0+127] = X * diag
    const float* Xb = X + (size_t)b * CC * NN;
    float* Ob = out + (size_t)b * CC * NN;
#pragma unroll 4
    for (int t = 0; t < 32; t++) {
        int f = tid + t * 256;
        int row = f >> 5;
        int c4 = (f & 31) << 2;
        float4 v = *(const float4*)&Xb[(size_t)row * NN + n0 + c4];
        float4 dv = *(const float4*)&sdiag[c4];
        v.x *= dv.x; v.y *= dv.y; v.z *= dv.z; v.w *= dv.w;
        *(float4*)&Ob[(size_t)row * NN + n0 + c4] = v;
    }
}

// ---------------------------------------------------------------------------
extern "C" void kernel_launch(void* const* d_in, const int* in_sizes, int n_in,
                              void* d_out, int out_size) {
    const float* X  = (const float*)d_in[0];
    const float* Wq = (const float*)d_in[1];
    const float* Wk = (const float*)d_in[2];
    float* out = (float*)d_out;

    cudaFuncSetAttribute(k_Zt, cudaFuncAttributeMaxDynamicSharedMemorySize, 131072);
    cudaFuncSetAttribute(k_main, cudaFuncAttributeMaxDynamicSharedMemorySize, SM_TOTAL);

    k_prepA<<<dim3(8, 32), dim3(32, 8)>>>(Wq, Wk);
    k_prep<<<dim3(NN / 32, CC / 32, BB), dim3(32, 8)>>>(X);
    k_Zt<<<dim3(32, 2, BB), 256, 131072>>>();
    k_main<<<BB * (NN / 128), 256, SM_TOTAL>>>(X, out);
}

// round 4
// speedup vs baseline: 2.3423x; 1.8918x over previous
#include <cuda_runtime.h>
#include <cuda_bf16.h>
#include <cstdint>

#define CC 256
#define NN 4096
#define BB 8

// ---------------- device globals (no runtime allocs allowed) ----------------
static __device__ __nv_bfloat16 g_Ah[CC * CC];      // A hi  [d][c]
static __device__ __nv_bfloat16 g_Al[CC * CC];      // A lo
static __device__ __nv_bfloat16 g_Xt_hi[(size_t)BB * NN * CC];  // X^T hi [b][n][c]
static __device__ __nv_bfloat16 g_Xt_lo[(size_t)BB * NN * CC];
static __device__ __nv_bfloat16 g_Zt_hi[(size_t)BB * NN * CC];  // Z^T hi [b][n][d]
static __device__ __nv_bfloat16 g_Zt_lo[(size_t)BB * NN * CC];

// ---------------- helpers ----------------
__device__ __forceinline__ float fexp2(float x) {
    float y;
    asm("ex2.approx.ftz.f32 %0, %1;" : "=f"(y) : "f"(x));
    return y;
}
__device__ __forceinline__ uint32_t smem_u32(const void* p) {
    uint32_t a;
    asm("{ .reg .u64 t; cvta.to.shared.u64 t, %1; cvt.u32.u64 %0, t; }" : "=r"(a) : "l"(p));
    return a;
}
#define SWZ(o) ((o) ^ (((o) >> 3) & 0x70))

#define CP16(dst, src) \
    asm volatile("cp.async.cg.shared.global [%0], [%1], 16;" :: "r"(dst), "l"(src) : "memory")
#define CP_COMMIT() asm volatile("cp.async.commit_group;" ::: "memory")
#define CP_WAIT0()  asm volatile("cp.async.wait_group 0;" ::: "memory")

__device__ __forceinline__ void ldsm4(uint32_t* r, uint32_t a) {
    asm volatile("ldmatrix.sync.aligned.m8n8.x4.shared.b16 {%0,%1,%2,%3}, [%4];"
        : "=r"(r[0]), "=r"(r[1]), "=r"(r[2]), "=r"(r[3]) : "r"(a));
}
__device__ __forceinline__ void mma16816(float* d, const uint32_t* a, const uint32_t* b) {
    asm volatile("mma.sync.aligned.m16n8k16.row.col.f32.bf16.bf16.f32 "
        "{%0,%1,%2,%3}, {%4,%5,%6,%7}, {%8,%9}, {%0,%1,%2,%3};"
        : "+f"(d[0]), "+f"(d[1]), "+f"(d[2]), "+f"(d[3])
        : "r"(a[0]), "r"(a[1]), "r"(a[2]), "r"(a[3]), "r"(b[0]), "r"(b[1]));
}
__device__ __forceinline__ uint32_t pack_bf16x2(__nv_bfloat16 a, __nv_bfloat16 b) {
    return (uint32_t)__bfloat16_as_ushort(a) | ((uint32_t)__bfloat16_as_ushort(b) << 16);
}

// ---------------------------------------------------------------------------
// A[d][c] = log2e * sum_e Wq[e][c] * Wk[e][d], stored as bf16 hi/lo
// ---------------------------------------------------------------------------
__global__ void k_prepA(const float* __restrict__ Wq, const float* __restrict__ Wk) {
    const float LOG2E = 1.4426950408889634f;
    int c = blockIdx.x * 32 + threadIdx.x;
    int d = blockIdx.y * 8 + threadIdx.y;
    float s0 = 0.f, s1 = 0.f;
#pragma unroll 8
    for (int e = 0; e < CC; e += 2) {
        s0 = fmaf(Wq[e * CC + c], Wk[e * CC + d], s0);
        s1 = fmaf(Wq[(e + 1) * CC + c], Wk[(e + 1) * CC + d], s1);
    }
    float v = (s0 + s1) * LOG2E;
    __nv_bfloat16 h = __float2bfloat16(v);
    g_Ah[d * CC + c] = h;
    g_Al[d * CC + c] = __float2bfloat16(v - __bfloat162float(h));
}

// ---------------------------------------------------------------------------
// Transpose + bf16 hi/lo split: X[b][c][n] -> Xt_hi/lo[b][n][c]
// ---------------------------------------------------------------------------
__global__ __launch_bounds__(256) void k_prep(const float* __restrict__ X) {
    __shared__ float s[32][33];
    const int b = blockIdx.z, c0 = blockIdx.y * 32, n0 = blockIdx.x * 32;
    const int tx = threadIdx.x, ty = threadIdx.y;
    const float* Xb = X + (size_t)b * CC * NN;
#pragma unroll
    for (int i = 0; i < 4; i++)
        s[ty + 8 * i][tx] = Xb[(size_t)(c0 + ty + 8 * i) * NN + n0 + tx];
    __syncthreads();
    const size_t base = (size_t)b * NN * CC;
#pragma unroll
    for (int i = 0; i < 4; i++) {
        int n = n0 + ty + 8 * i;
        float v = s[tx][ty + 8 * i];
        __nv_bfloat16 h = __float2bfloat16(v);
        g_Xt_hi[base + (size_t)n * CC + c0 + tx] = h;
        g_Xt_lo[base + (size_t)n * CC + c0 + tx] =
            __float2bfloat16(v - __bfloat162float(h));
    }
}

// ---------------------------------------------------------------------------
// k_Zt: Zt[n][d] = sum_c Xt[n][c] * A[d][c]   (3-term bf16 split, mma.sync)
// grid (32 nt, 2 dt, 8 b), 256 threads (8 warps x 16 rows x 128 cols)
// ---------------------------------------------------------------------------
__global__ __launch_bounds__(256, 1) void k_Zt() {
    extern __shared__ char smem[];
    const uint32_t sb = smem_u32(smem);
    const int tid = threadIdx.x;
    const int wid = tid >> 5, lane = tid & 31;
    const int g = lane >> 2;
    const int n0 = blockIdx.x << 7;
    const int d0 = blockIdx.y << 7;
    const int b = blockIdx.z;
    const size_t bbase = (size_t)b * NN * CC;
    const char* Xsrc[2] = {(const char*)(g_Xt_hi + bbase), (const char*)(g_Xt_lo + bbase)};
    const char* Asrc[2] = {(const char*)g_Ah, (const char*)g_Al};

    const int aRow = wid * 16 + (lane & 15);
    const uint32_t aOff = (uint32_t)(aRow * 128);
    const uint32_t aSwz = (uint32_t)((aRow * 16) & 0x70);
    const int aColX = (lane >> 4) << 4;
    const int bRowOff = (lane & 7) + ((lane >> 4) & 1) * 8;
    const int bColX = ((lane >> 3) & 1) << 4;

    float acc[16][4];
#pragma unroll
    for (int i = 0; i < 16; i++)
#pragma unroll
        for (int j = 0; j < 4; j++) acc[i][j] = 0.f;

#pragma unroll
    for (int t = 0; t < 16; t++) {
        int o = tid + t * 256;
        int role = o >> 10, r = (o >> 3) & 127, j = o & 7;
        const char* src = (role < 2)
            ? Xsrc[role] + ((size_t)(n0 + r) * CC) * 2 + j * 16
            : Asrc[role - 2] + ((size_t)(d0 + r) * CC) * 2 + j * 16;
        uint32_t dst = sb + (uint32_t)role * 16384u + SWZ((uint32_t)(r * 128 + j * 16));
        CP16(dst, src);
    }
    CP_COMMIT();

#pragma unroll 1
    for (int cc = 0; cc < 4; cc++) {
        const int buf = cc & 1;
        CP_WAIT0();
        __syncthreads();
        if (cc < 3) {
            const int cn = cc + 1, bn = buf ^ 1;
#pragma unroll
            for (int t = 0; t < 16; t++) {
                int o = tid + t * 256;
                int role = o >> 10, r = (o >> 3) & 127, j = o & 7;
                const char* src = (role < 2)
                    ? Xsrc[role] + ((size_t)(n0 + r) * CC + cn * 64) * 2 + j * 16
                    : Asrc[role - 2] + ((size_t)(d0 + r) * CC + cn * 64) * 2 + j * 16;
                uint32_t dst = sb + (uint32_t)(bn * 4 + role) * 16384u +
                               SWZ((uint32_t)(r * 128 + j * 16));
                CP16(dst, src);
            }
        }
        CP_COMMIT();

        const uint32_t xh = sb + (uint32_t)(buf * 4 + 0) * 16384u;
        const uint32_t xl = xh + 16384u;
        const uint32_t ah = sb + (uint32_t)(buf * 4 + 2) * 16384u;
        const uint32_t al = ah + 16384u;
#pragma unroll
        for (int ks = 0; ks < 4; ks++) {
            const int cb = ks * 32;
            uint32_t Ah[4], Al[4];
            uint32_t aoff = aOff + (uint32_t)((cb + aColX) ^ aSwz);
            ldsm4(Ah, xh + aoff);
            ldsm4(Al, xl + aoff);
#pragma unroll
            for (int j2 = 0; j2 < 8; j2++) {
                uint32_t Bh[4], Bl[4];
                int brow = j2 * 16 + bRowOff;
                uint32_t boff = (uint32_t)(brow * 128) +
                                (uint32_t)((cb + bColX) ^ ((brow * 16) & 0x70));
                ldsm4(Bh, ah + boff);
                ldsm4(Bl, al + boff);
                mma16816(acc[j2 * 2],     Ah, Bh);
                mma16816(acc[j2 * 2 + 1], Ah, Bh + 2);
                mma16816(acc[j2 * 2],     Ah, Bl);
                mma16816(acc[j2 * 2 + 1], Ah, Bl + 2);
                mma16816(acc[j2 * 2],     Al, Bh);
                mma16816(acc[j2 * 2 + 1], Al, Bh + 2);
            }
        }
    }

    char* Zh = (char*)(g_Zt_hi + bbase);
    char* Zl = (char*)(g_Zt_lo + bbase);
#pragma unroll
    for (int h = 0; h < 2; h++) {
        int n = n0 + wid * 16 + h * 8 + g;
#pragma unroll
        for (int bt = 0; bt < 16; bt++) {
            float v0 = acc[bt][2 * h], v1 = acc[bt][2 * h + 1];
            __nv_bfloat16 h0 = __float2bfloat16(v0);
            __nv_bfloat16 h1 = __float2bfloat16(v1);
            __nv_bfloat16 l0 = __float2bfloat16(v0 - __bfloat162float(h0));
            __nv_bfloat16 l1 = __float2bfloat16(v1 - __bfloat162float(h1));
            size_t off = ((size_t)n * CC + d0 + bt * 8 + 2 * (lane & 3)) * 2;
            *(uint32_t*)(Zh + off) = pack_bf16x2(h0, h1);
            *(uint32_t*)(Zl + off) = pack_bf16x2(l0, l1);
        }
    }
}

// ---------------------------------------------------------------------------
// k_main: S[n][m] = sum_d Zt[n][d] * Xt[m][d]  (3-term split, mma.sync)
// 512 threads, 16 warps in 4x4 grid, warp tile 32 rows x 32 cols.
// Online softmax with cross-warp (4-way) row reduction via smem.
// SMEM: Z persistent 128KB | X 2buf x {hi,lo} 64KB | reduction scratch 5KB
// ---------------------------------------------------------------------------
#define SM_ZS 0u
#define SM_XS 131072u
#define SM_RED 196608u
#define SM_TOTAL (196608 + 5120)

__global__ __launch_bounds__(512, 1) void k_main(const float* __restrict__ X,
                                                 float* __restrict__ out) {
    extern __shared__ char smem[];
    const uint32_t sb = smem_u32(smem);
    const int tid = threadIdx.x;
    const int wid = tid >> 5, lane = tid & 31;
    const int wr = wid >> 2, wc = wid & 3;       // 4x4 warp grid
    const int g = lane >> 2;
    const int b = blockIdx.x >> 5;
    const int nt = blockIdx.x & 31;
    const int n0 = nt << 7;
    const size_t bbase = (size_t)b * NN * CC;
    const char* Zsrc[2] = {(const char*)(g_Zt_hi + bbase), (const char*)(g_Zt_lo + bbase)};
    const char* Xsrc[2] = {(const char*)(g_Xt_hi + bbase), (const char*)(g_Xt_lo + bbase)};

    float* pmax  = (float*)(smem + SM_RED);           // [4 wc][128]
    float* psum  = (float*)(smem + SM_RED + 2048);    // [4 wc][128]
    float* sdlog = (float*)(smem + SM_RED + 4096);    // [128]
    float* sdiag = (float*)(smem + SM_RED + 4608);    // [128]

    // lane constants
    const int aColX = (lane >> 4) << 4;
    const int bRowOff = (lane & 7) + ((lane >> 4) & 1) * 8;
    const int bColX = ((lane >> 3) & 1) << 4;

    // prologue: persistent Z (8 tiles) + X chunk 0 into buf 0
#pragma unroll
    for (int t = 0; t < 16; t++) {
        int o = tid + t * 512;
        int ch = o >> 11, hs = (o >> 10) & 1, r = (o >> 3) & 127, j = o & 7;
        const char* src = Zsrc[hs] + ((size_t)(n0 + r) * CC + ch * 64) * 2 + j * 16;
        uint32_t dst = sb + SM_ZS + (uint32_t)(ch * 2 + hs) * 16384u +
                       SWZ((uint32_t)(r * 128 + j * 16));
        CP16(dst, src);
    }
#pragma unroll
    for (int t = 0; t < 4; t++) {
        int o = tid + t * 512;
        int hs = o >> 10, r = (o >> 3) & 127, j = o & 7;
        const char* src = Xsrc[hs] + ((size_t)r * CC) * 2 + j * 16;
        uint32_t dst = sb + SM_XS + (uint32_t)hs * 16384u + SWZ((uint32_t)(r * 128 + j * 16));
        CP16(dst, src);
    }
    CP_COMMIT();

    float acc[2][4][4];
#pragma unroll
    for (int i = 0; i < 2; i++)
#pragma unroll
        for (int j = 0; j < 4; j++)
#pragma unroll
            for (int k = 0; k < 4; k++) acc[i][j][k] = 0.f;
    float mrun[2][2], rsum[2][2];
#pragma unroll
    for (int i = 0; i < 2; i++)
#pragma unroll
        for (int j = 0; j < 2; j++) { mrun[i][j] = -3.0e38f; rsum[i][j] = 0.f; }

#pragma unroll 1
    for (int G = 0; G < 128; G++) {
        const int cc = G & 3, mt = G >> 2, buf = G & 1;
        CP_WAIT0();
        __syncthreads();

        // prefetch next chunk into other buffer
        if (G < 127) {
            const int Gn = G + 1;
            const int ccn = Gn & 3, m0n = (Gn >> 2) << 7, bn = buf ^ 1;
#pragma unroll
            for (int t = 0; t < 4; t++) {
                int o = tid + t * 512;
                int hs = o >> 10, r = (o >> 3) & 127, j = o & 7;
                const char* src = Xsrc[hs] + ((size_t)(m0n + r) * CC + ccn * 64) * 2 + j * 16;
                uint32_t dst = sb + SM_XS + (uint32_t)(bn * 2 + hs) * 16384u +
                               SWZ((uint32_t)(r * 128 + j * 16));
                CP16(dst, src);
            }
        }
        CP_COMMIT();

        const uint32_t zh = sb + SM_ZS + (uint32_t)(cc * 2) * 16384u;
        const uint32_t zl = zh + 16384u;
        const uint32_t xh = sb + SM_XS + (uint32_t)(buf * 2) * 16384u;
        const uint32_t xl = xh + 16384u;
#pragma unroll
        for (int ks = 0; ks < 4; ks++) {
            const int cb = ks * 32;
            uint32_t Ah[2][4], Al[2][4], Bh[2][4], Bl[2][4];
#pragma unroll
            for (int rb = 0; rb < 2; rb++) {
                int row = wr * 32 + rb * 16 + (lane & 15);
                uint32_t off = (uint32_t)(row * 128) +
                               (uint32_t)((cb + aColX) ^ ((row * 16) & 0x70));
                ldsm4(Ah[rb], zh + off);
                ldsm4(Al[rb], zl + off);
            }
#pragma unroll
            for (int cs = 0; cs < 2; cs++) {
                int row = wc * 32 + cs * 16 + bRowOff;
                uint32_t off = (uint32_t)(row * 128) +
                               (uint32_t)((cb + bColX) ^ ((row * 16) & 0x70));
                ldsm4(Bh[cs], xh + off);
                ldsm4(Bl[cs], xl + off);
            }
#pragma unroll
            for (int rb = 0; rb < 2; rb++)
#pragma unroll
                for (int cs = 0; cs < 2; cs++) {
                    mma16816(acc[rb][cs * 2],     Ah[rb], Bh[cs]);
                    mma16816(acc[rb][cs * 2 + 1], Ah[rb], Bh[cs] + 2);
                    mma16816(acc[rb][cs * 2],     Ah[rb], Bl[cs]);
                    mma16816(acc[rb][cs * 2 + 1], Ah[rb], Bl[cs] + 2);
                    mma16816(acc[rb][cs * 2],     Al[rb], Bh[cs]);
                    mma16816(acc[rb][cs * 2 + 1], Al[rb], Bh[cs] + 2);
                }
        }

        // ---- tile boundary: online softmax with cross-warp reduction ----
        if (cc == 3) {
            // per-warp partial (max, sum) per owned row
#pragma unroll
            for (int rb = 0; rb < 2; rb++)
#pragma unroll
                for (int rh = 0; rh < 2; rh++) {
                    float tm = -3.0e38f;
#pragma unroll
                    for (int j = 0; j < 4; j++)
                        tm = fmaxf(tm, fmaxf(acc[rb][j][2 * rh], acc[rb][j][2 * rh + 1]));
                    tm = fmaxf(tm, __shfl_xor_sync(0xffffffffu, tm, 1));
                    tm = fmaxf(tm, __shfl_xor_sync(0xffffffffu, tm, 2));
                    float ps = 0.f;
#pragma unroll
                    for (int j = 0; j < 4; j++) {
                        ps += fexp2(acc[rb][j][2 * rh] - tm);
                        ps += fexp2(acc[rb][j][2 * rh + 1] - tm);
                    }
                    ps += __shfl_xor_sync(0xffffffffu, ps, 1);
                    ps += __shfl_xor_sync(0xffffffffu, ps, 2);
                    if ((lane & 3) == 0) {
                        int rl = wr * 32 + rb * 16 + rh * 8 + g;
                        pmax[wc * 128 + rl] = tm;
                        psum[wc * 128 + rl] = ps;
                    }
                }
            // diagonal capture (raw log2-logit)
            if (mt == nt && wr == wc) {
#pragma unroll
                for (int rb = 0; rb < 2; rb++)
#pragma unroll
                    for (int rh = 0; rh < 2; rh++) {
                        int cl = rb * 16 + rh * 8 + g;
                        if ((lane & 3) == ((cl & 7) >> 1))
                            sdlog[wr * 32 + cl] = acc[rb][rb * 2 + rh][2 * rh + (cl & 1)];
                    }
            }
            __syncthreads();
            // replicated combine (all wc warps compute identical state)
#pragma unroll
            for (int rb = 0; rb < 2; rb++)
#pragma unroll
                for (int rh = 0; rh < 2; rh++) {
                    int rl = wr * 32 + rb * 16 + rh * 8 + g;
                    float mn = mrun[rb][rh];
#pragma unroll
                    for (int j = 0; j < 4; j++) mn = fmaxf(mn, pmax[j * 128 + rl]);
                    float rs = rsum[rb][rh] * fexp2(mrun[rb][rh] - mn);
#pragma unroll
                    for (int j = 0; j < 4; j++)
                        rs += fexp2(pmax[j * 128 + rl] - mn) * psum[j * 128 + rl];
                    mrun[rb][rh] = mn;
                    rsum[rb][rh] = rs;
                }
            // reset accumulators
#pragma unroll
            for (int i = 0; i < 2; i++)
#pragma unroll
                for (int j = 0; j < 4; j++)
#pragma unroll
                    for (int k = 0; k < 4; k++) acc[i][j][k] = 0.f;
        }
    }

    // final diag
    if (wc == 0 && (lane & 3) == 0) {
#pragma unroll
        for (int rb = 0; rb < 2; rb++)
#pragma unroll
            for (int rh = 0; rh < 2; rh++) {
                int rl = wr * 32 + rb * 16 + rh * 8 + g;
                sdiag[rl] = fexp2(sdlog[rl] - mrun[rb][rh]) / rsum[rb][rh] *
                            (1.0f / (1.0f + 1e-8f));
            }
    }
    __syncthreads();

    // out[b][c][n0..n0+127] = X * diag
    const float* Xb = X + (size_t)b * CC * NN;
    float* Ob = out + (size_t)b * CC * NN;
#pragma unroll 4
    for (int t = 0; t < 16; t++) {
        int f = tid + t * 512;
        int row = f >> 5;
        int c4 = (f & 31) << 2;
        float4 v = *(const float4*)&Xb[(size_t)row * NN + n0 + c4];
        float4 dv = *(const float4*)&sdiag[c4];
        v.x *= dv.x; v.y *= dv.y; v.z *= dv.z; v.w *= dv.w;
        *(float4*)&Ob[(size_t)row * NN + n0 + c4] = v;
    }
}

// ---------------------------------------------------------------------------
extern "C" void kernel_launch(void* const* d_in, const int* in_sizes, int n_in,
                              void* d_out, int out_size) {
    const float* X  = (const float*)d_in[0];
    const float* Wq = (const float*)d_in[1];
    const float* Wk = (const float*)d_in[2];
    float* out = (float*)d_out;

    cudaFuncSetAttribute(k_Zt, cudaFuncAttributeMaxDynamicSharedMemorySize, 131072);
    cudaFuncSetAttribute(k_main, cudaFuncAttributeMaxDynamicSharedMemorySize, SM_TOTAL);

    k_prepA<<<dim3(8, 32), dim3(32, 8)>>>(Wq, Wk);
    k_prep<<<dim3(NN / 32, CC / 32, BB), dim3(32, 8)>>>(X);
    k_Zt<<<dim3(32, 2, BB), 256, 131072>>>();
    k_main<<<BB * (NN / 128), 512, SM_TOTAL>>>(X, out);
}

// round 6
// speedup vs baseline: 2.5441x; 1.0861x over previous
#include <cuda_runtime.h>
#include <cuda_bf16.h>
#include <cstdint>

#define CC 256
#define NN 4096
#define BB 8

// ---------------- device globals (no runtime allocs allowed) ----------------
static __device__ __nv_bfloat16 g_Ah[CC * CC];      // A hi  [d][c]
static __device__ __nv_bfloat16 g_Al[CC * CC];      // A lo
static __device__ __nv_bfloat16 g_Xt_hi[(size_t)BB * NN * CC];  // X^T hi [b][n][c]
static __device__ __nv_bfloat16 g_Xt_lo[(size_t)BB * NN * CC];
static __device__ __nv_bfloat16 g_Zt_hi[(size_t)BB * NN * CC];  // Z^T hi [b][n][d]
static __device__ __nv_bfloat16 g_Zt_lo[(size_t)BB * NN * CC];
// split-softmax partials: [b*32+nt][mq][row]
static __device__ float g_pm[(size_t)BB * 32 * 4 * 128];
static __device__ float g_ps[(size_t)BB * 32 * 4 * 128];
static __device__ float g_dlog[(size_t)BB * 32 * 128];

// ---------------- helpers ----------------
__device__ __forceinline__ float fexp2(float x) {
    float y;
    asm("ex2.approx.ftz.f32 %0, %1;" : "=f"(y) : "f"(x));
    return y;
}
__device__ __forceinline__ uint32_t smem_u32(const void* p) {
    uint32_t a;
    asm("{ .reg .u64 t; cvta.to.shared.u64 t, %1; cvt.u32.u64 %0, t; }" : "=r"(a) : "l"(p));
    return a;
}
#define SWZ(o) ((o) ^ (((o) >> 3) & 0x70))

#define CP16(dst, src) \
    asm volatile("cp.async.cg.shared.global [%0], [%1], 16;" :: "r"(dst), "l"(src) : "memory")
#define CP_COMMIT() asm volatile("cp.async.commit_group;" ::: "memory")
#define CP_WAIT0()  asm volatile("cp.async.wait_group 0;" ::: "memory")
#define CP_WAIT1()  asm volatile("cp.async.wait_group 1;" ::: "memory")

__device__ __forceinline__ void ldsm4(uint32_t* r, uint32_t a) {
    asm volatile("ldmatrix.sync.aligned.m8n8.x4.shared.b16 {%0,%1,%2,%3}, [%4];"
        : "=r"(r[0]), "=r"(r[1]), "=r"(r[2]), "=r"(r[3]) : "r"(a));
}
__device__ __forceinline__ void mma16816(float* d, const uint32_t* a, const uint32_t* b) {
    asm volatile("mma.sync.aligned.m16n8k16.row.col.f32.bf16.bf16.f32 "
        "{%0,%1,%2,%3}, {%4,%5,%6,%7}, {%8,%9}, {%0,%1,%2,%3};"
        : "+f"(d[0]), "+f"(d[1]), "+f"(d[2]), "+f"(d[3])
        : "r"(a[0]), "r"(a[1]), "r"(a[2]), "r"(a[3]), "r"(b[0]), "r"(b[1]));
}
__device__ __forceinline__ uint32_t pack_bf16x2(__nv_bfloat16 a, __nv_bfloat16 b) {
    return (uint32_t)__bfloat16_as_ushort(a) | ((uint32_t)__bfloat16_as_ushort(b) << 16);
}

// ---------------------------------------------------------------------------
// A[d][c] = log2e * sum_e Wq[e][c] * Wk[e][d], stored as bf16 hi/lo
// ---------------------------------------------------------------------------
__global__ void k_prepA(const float* __restrict__ Wq, const float* __restrict__ Wk) {
    const float LOG2E = 1.4426950408889634f;
    int c = blockIdx.x * 32 + threadIdx.x;
    int d = blockIdx.y * 8 + threadIdx.y;
    float s0 = 0.f, s1 = 0.f;
#pragma unroll 8
    for (int e = 0; e < CC; e += 2) {
        s0 = fmaf(Wq[e * CC + c], Wk[e * CC + d], s0);
        s1 = fmaf(Wq[(e + 1) * CC + c], Wk[(e + 1) * CC + d], s1);
    }
    float v = (s0 + s1) * LOG2E;
    __nv_bfloat16 h = __float2bfloat16(v);
    g_Ah[d * CC + c] = h;
    g_Al[d * CC + c] = __float2bfloat16(v - __bfloat162float(h));
}

// ---------------------------------------------------------------------------
// Transpose + bf16 hi/lo split: X[b][c][n] -> Xt_hi/lo[b][n][c]
// ---------------------------------------------------------------------------
__global__ __launch_bounds__(256) void k_prep(const float* __restrict__ X) {
    __shared__ float s[32][33];
    const int b = blockIdx.z, c0 = blockIdx.y * 32, n0 = blockIdx.x * 32;
    const int tx = threadIdx.x, ty = threadIdx.y;
    const float* Xb = X + (size_t)b * CC * NN;
#pragma unroll
    for (int i = 0; i < 4; i++)
        s[ty + 8 * i][tx] = Xb[(size_t)(c0 + ty + 8 * i) * NN + n0 + tx];
    __syncthreads();
    const size_t base = (size_t)b * NN * CC;
#pragma unroll
    for (int i = 0; i < 4; i++) {
        int n = n0 + ty + 8 * i;
        float v = s[tx][ty + 8 * i];
        __nv_bfloat16 h = __float2bfloat16(v);
        g_Xt_hi[base + (size_t)n * CC + c0 + tx] = h;
        g_Xt_lo[base + (size_t)n * CC + c0 + tx] =
            __float2bfloat16(v - __bfloat162float(h));
    }
}

// ---------------------------------------------------------------------------
// k_Zt: Zt[n][d] = sum_c Xt[n][c] * A[d][c]   (3-term bf16 split, mma.sync)
// ---------------------------------------------------------------------------
__global__ __launch_bounds__(256, 1) void k_Zt() {
    extern __shared__ char smem[];
    const uint32_t sb = smem_u32(smem);
    const int tid = threadIdx.x;
    const int wid = tid >> 5, lane = tid & 31;
    const int g = lane >> 2;
    const int n0 = blockIdx.x << 7;
    const int d0 = blockIdx.y << 7;
    const int b = blockIdx.z;
    const size_t bbase = (size_t)b * NN * CC;
    const char* Xsrc[2] = {(const char*)(g_Xt_hi + bbase), (const char*)(g_Xt_lo + bbase)};
    const char* Asrc[2] = {(const char*)g_Ah, (const char*)g_Al};

    const int aRow = wid * 16 + (lane & 15);
    const uint32_t aOff = (uint32_t)(aRow * 128);
    const uint32_t aSwz = (uint32_t)((aRow * 16) & 0x70);
    const int aColX = (lane >> 4) << 4;
    const int bRowOff = (lane & 7) + ((lane >> 4) & 1) * 8;
    const int bColX = ((lane >> 3) & 1) << 4;

    float acc[16][4];
#pragma unroll
    for (int i = 0; i < 16; i++)
#pragma unroll
        for (int j = 0; j < 4; j++) acc[i][j] = 0.f;

#pragma unroll
    for (int t = 0; t < 16; t++) {
        int o = tid + t * 256;
        int role = o >> 10, r = (o >> 3) & 127, j = o & 7;
        const char* src = (role < 2)
            ? Xsrc[role] + ((size_t)(n0 + r) * CC) * 2 + j * 16
            : Asrc[role - 2] + ((size_t)(d0 + r) * CC) * 2 + j * 16;
        uint32_t dst = sb + (uint32_t)role * 16384u + SWZ((uint32_t)(r * 128 + j * 16));
        CP16(dst, src);
    }
    CP_COMMIT();

#pragma unroll 1
    for (int cc = 0; cc < 4; cc++) {
        const int buf = cc & 1;
        CP_WAIT0();
        __syncthreads();
        if (cc < 3) {
            const int cn = cc + 1, bn = buf ^ 1;
#pragma unroll
            for (int t = 0; t < 16; t++) {
                int o = tid + t * 256;
                int role = o >> 10, r = (o >> 3) & 127, j = o & 7;
                const char* src = (role < 2)
                    ? Xsrc[role] + ((size_t)(n0 + r) * CC + cn * 64) * 2 + j * 16
                    : Asrc[role - 2] + ((size_t)(d0 + r) * CC + cn * 64) * 2 + j * 16;
                uint32_t dst = sb + (uint32_t)(bn * 4 + role) * 16384u +
                               SWZ((uint32_t)(r * 128 + j * 16));
                CP16(dst, src);
            }
        }
        CP_COMMIT();

        const uint32_t xh = sb + (uint32_t)(buf * 4 + 0) * 16384u;
        const uint32_t xl = xh + 16384u;
        const uint32_t ah = sb + (uint32_t)(buf * 4 + 2) * 16384u;
        const uint32_t al = ah + 16384u;
#pragma unroll
        for (int ks = 0; ks < 4; ks++) {
            const int cb = ks * 32;
            uint32_t Ah[4], Al[4];
            uint32_t aoff = aOff + (uint32_t)((cb + aColX) ^ aSwz);
            ldsm4(Ah, xh + aoff);
            ldsm4(Al, xl + aoff);
#pragma unroll
            for (int j2 = 0; j2 < 8; j2++) {
                uint32_t Bh[4], Bl[4];
                int brow = j2 * 16 + bRowOff;
                uint32_t boff = (uint32_t)(brow * 128) +
                                (uint32_t)((cb + bColX) ^ ((brow * 16) & 0x70));
                ldsm4(Bh, ah + boff);
                ldsm4(Bl, al + boff);
                mma16816(acc[j2 * 2],     Ah, Bh);
                mma16816(acc[j2 * 2 + 1], Ah, Bh + 2);
                mma16816(acc[j2 * 2],     Ah, Bl);
                mma16816(acc[j2 * 2 + 1], Ah, Bl + 2);
                mma16816(acc[j2 * 2],     Al, Bh);
                mma16816(acc[j2 * 2 + 1], Al, Bh + 2);
            }
        }
    }

    char* Zh = (char*)(g_Zt_hi + bbase);
    char* Zl = (char*)(g_Zt_lo + bbase);
#pragma unroll
    for (int h = 0; h < 2; h++) {
        int n = n0 + wid * 16 + h * 8 + g;
#pragma unroll
        for (int bt = 0; bt < 16; bt++) {
            float v0 = acc[bt][2 * h], v1 = acc[bt][2 * h + 1];
            __nv_bfloat16 h0 = __float2bfloat16(v0);
            __nv_bfloat16 h1 = __float2bfloat16(v1);
            __nv_bfloat16 l0 = __float2bfloat16(v0 - __bfloat162float(h0));
            __nv_bfloat16 l1 = __float2bfloat16(v1 - __bfloat162float(h1));
            size_t off = ((size_t)n * CC + d0 + bt * 8 + 2 * (lane & 3)) * 2;
            *(uint32_t*)(Zh + off) = pack_bf16x2(h0, h1);
            *(uint32_t*)(Zl + off) = pack_bf16x2(l0, l1);
        }
    }
}

// ---------------------------------------------------------------------------
// k_part: partial softmax over one m-quarter (8 m-tiles of 128 cols).
// grid = B*32*4 (bx -> b, nt, mq), 512 threads (16 warps, 4x4, 32x32 tiles).
// Z persistent in smem (128KB), X triple-buffered K=64 chunks (3x32KB),
// cp.async.wait_group 1 so every load has 2 chunk-times to land.
// Epilogue scratch aliases the just-consumed X buffer; a __syncthreads()
// BEFORE the scratch writes guarantees all warps' ldsm of that buffer are
// done (this was the round-5 race).
// ---------------------------------------------------------------------------
#define SM_ZS 0u
#define SM_XS 131072u
#define SM_TOTAL (131072 + 3 * 32768)

__global__ __launch_bounds__(512, 1) void k_part() {
    extern __shared__ char smem[];
    const uint32_t sb = smem_u32(smem);
    const int tid = threadIdx.x;
    const int wid = tid >> 5, lane = tid & 31;
    const int wr = wid >> 2, wc = wid & 3;
    const int g = lane >> 2;
    const int bx = blockIdx.x;
    const int b = bx >> 7;
    const int nt = (bx >> 2) & 31;
    const int mq = bx & 3;
    const int n0 = nt << 7;
    const size_t bbase = (size_t)b * NN * CC;
    const char* Zsrc[2] = {(const char*)(g_Zt_hi + bbase), (const char*)(g_Zt_lo + bbase)};
    const char* Xsrc[2] = {(const char*)(g_Xt_hi + bbase), (const char*)(g_Xt_lo + bbase)};

    const int aColX = (lane >> 4) << 4;
    const int bRowOff = (lane & 7) + ((lane >> 4) & 1) * 8;
    const int bColX = ((lane >> 3) & 1) << 4;

    // prologue: group0 = Z (8 tiles) + X chunk0 ; group1 = X chunk1
#pragma unroll
    for (int t = 0; t < 16; t++) {
        int o = tid + t * 512;
        int ch = o >> 11, hs = (o >> 10) & 1, r = (o >> 3) & 127, j = o & 7;
        const char* src = Zsrc[hs] + ((size_t)(n0 + r) * CC + ch * 64) * 2 + j * 16;
        uint32_t dst = sb + SM_ZS + (uint32_t)(ch * 2 + hs) * 16384u +
                       SWZ((uint32_t)(r * 128 + j * 16));
        CP16(dst, src);
    }
    {
        const int m00 = (mq * 8) << 7;
#pragma unroll
        for (int t = 0; t < 4; t++) {
            int o = tid + t * 512;
            int hs = o >> 10, r = (o >> 3) & 127, j = o & 7;
            const char* src = Xsrc[hs] + ((size_t)(m00 + r) * CC) * 2 + j * 16;
            uint32_t dst = sb + SM_XS + (uint32_t)hs * 16384u +
                           SWZ((uint32_t)(r * 128 + j * 16));
            CP16(dst, src);
        }
        CP_COMMIT();   // group 0
#pragma unroll
        for (int t = 0; t < 4; t++) {
            int o = tid + t * 512;
            int hs = o >> 10, r = (o >> 3) & 127, j = o & 7;
            const char* src = Xsrc[hs] + ((size_t)(m00 + r) * CC + 64) * 2 + j * 16;
            uint32_t dst = sb + SM_XS + 32768u + (uint32_t)hs * 16384u +
                           SWZ((uint32_t)(r * 128 + j * 16));
            CP16(dst, src);
        }
        CP_COMMIT();   // group 1
    }

    float acc[2][4][4];
#pragma unroll
    for (int i = 0; i < 2; i++)
#pragma unroll
        for (int j = 0; j < 4; j++)
#pragma unroll
            for (int k = 0; k < 4; k++) acc[i][j][k] = 0.f;
    float mrun[2][2], rsum[2][2];
#pragma unroll
    for (int i = 0; i < 2; i++)
#pragma unroll
        for (int j = 0; j < 2; j++) { mrun[i][j] = -3.0e38f; rsum[i][j] = 0.f; }

    int buf = 0, bufp = 2;   // buf = G%3, bufp = (G+2)%3

#pragma unroll 1
    for (int G = 0; G < 32; G++) {
        const int cc = G & 3, mtl = G >> 2;
        CP_WAIT1();          // chunk G (issued 2 iters ago) has landed
        __syncthreads();

        // prefetch chunk G+2 into buf (G+2)%3
        if (G + 2 < 32) {
            const int Gn = G + 2;
            const int ccn = Gn & 3, m0n = (mq * 8 + (Gn >> 2)) << 7;
#pragma unroll
            for (int t = 0; t < 4; t++) {
                int o = tid + t * 512;
                int hs = o >> 10, r = (o >> 3) & 127, j = o & 7;
                const char* src = Xsrc[hs] + ((size_t)(m0n + r) * CC + ccn * 64) * 2 + j * 16;
                uint32_t dst = sb + SM_XS + (uint32_t)bufp * 32768u +
                               (uint32_t)hs * 16384u + SWZ((uint32_t)(r * 128 + j * 16));
                CP16(dst, src);
            }
        }
        CP_COMMIT();

        const uint32_t zh = sb + SM_ZS + (uint32_t)(cc * 2) * 16384u;
        const uint32_t zl = zh + 16384u;
        const uint32_t xh = sb + SM_XS + (uint32_t)buf * 32768u;
        const uint32_t xl = xh + 16384u;
#pragma unroll
        for (int ks = 0; ks < 4; ks++) {
            const int cb = ks * 32;
            uint32_t Ah[2][4], Al[2][4], Bh[2][4], Bl[2][4];
#pragma unroll
            for (int rb = 0; rb < 2; rb++) {
                int row = wr * 32 + rb * 16 + (lane & 15);
                uint32_t off = (uint32_t)(row * 128) +
                               (uint32_t)((cb + aColX) ^ ((row * 16) & 0x70));
                ldsm4(Ah[rb], zh + off);
                ldsm4(Al[rb], zl + off);
            }
#pragma unroll
            for (int cs = 0; cs < 2; cs++) {
                int row = wc * 32 + cs * 16 + bRowOff;
                uint32_t off = (uint32_t)(row * 128) +
                               (uint32_t)((cb + bColX) ^ ((row * 16) & 0x70));
                ldsm4(Bh[cs], xh + off);
                ldsm4(Bl[cs], xl + off);
            }
#pragma unroll
            for (int rb = 0; rb < 2; rb++)
#pragma unroll
                for (int cs = 0; cs < 2; cs++) {
                    mma16816(acc[rb][cs * 2],     Ah[rb], Bh[cs]);
                    mma16816(acc[rb][cs * 2 + 1], Ah[rb], Bh[cs] + 2);
                    mma16816(acc[rb][cs * 2],     Ah[rb], Bl[cs]);
                    mma16816(acc[rb][cs * 2 + 1], Ah[rb], Bl[cs] + 2);
                    mma16816(acc[rb][cs * 2],     Al[rb], Bh[cs]);
                    mma16816(acc[rb][cs * 2 + 1], Al[rb], Bh[cs] + 2);
                }
        }

        // ---- tile boundary: online softmax ----
        if (cc == 3) {
            // RACE FIX (round 5 -> 6): all warps must finish their ldsm reads
            // of buf before anyone scrawls scratch over it.
            __syncthreads();

            // scratch in the just-consumed X buffer (no pending cp.async
            // group targets buf G%3)
            float* pmax = (float*)(smem + SM_XS + (uint32_t)buf * 32768u);
            float* psum = pmax + 512;

#pragma unroll
            for (int rb = 0; rb < 2; rb++)
#pragma unroll
                for (int rh = 0; rh < 2; rh++) {
                    float tm = -3.0e38f;
#pragma unroll
                    for (int j = 0; j < 4; j++)
                        tm = fmaxf(tm, fmaxf(acc[rb][j][2 * rh], acc[rb][j][2 * rh + 1]));
                    tm = fmaxf(tm, __shfl_xor_sync(0xffffffffu, tm, 1));
                    tm = fmaxf(tm, __shfl_xor_sync(0xffffffffu, tm, 2));
                    float ps = 0.f;
#pragma unroll
                    for (int j = 0; j < 4; j++) {
                        ps += fexp2(acc[rb][j][2 * rh] - tm);
                        ps += fexp2(acc[rb][j][2 * rh + 1] - tm);
                    }
                    ps += __shfl_xor_sync(0xffffffffu, ps, 1);
                    ps += __shfl_xor_sync(0xffffffffu, ps, 2);
                    if ((lane & 3) == 0) {
                        int rl = wr * 32 + rb * 16 + rh * 8 + g;
                        pmax[wc * 128 + rl] = tm;
                        psum[wc * 128 + rl] = ps;
                    }
                }
            // diagonal capture (raw log2-logit) -> gmem
            if (mq == (nt >> 3) && mtl == (nt & 7) && wr == wc) {
#pragma unroll
                for (int rb = 0; rb < 2; rb++)
#pragma unroll
                    for (int rh = 0; rh < 2; rh++) {
                        int cl = rb * 16 + rh * 8 + g;
                        if ((lane & 3) == ((cl & 7) >> 1))
                            g_dlog[(size_t)(b * 32 + nt) * 128 + wr * 32 + cl] =
                                acc[rb][rb * 2 + rh][2 * rh + (cl & 1)];
                    }
            }
            __syncthreads();
            // replicated combine
#pragma unroll
            for (int rb = 0; rb < 2; rb++)
#pragma unroll
                for (int rh = 0; rh < 2; rh++) {
                    int rl = wr * 32 + rb * 16 + rh * 8 + g;
                    float mn = mrun[rb][rh];
#pragma unroll
                    for (int j = 0; j < 4; j++) mn = fmaxf(mn, pmax[j * 128 + rl]);
                    float rs = rsum[rb][rh] * fexp2(mrun[rb][rh] - mn);
#pragma unroll
                    for (int j = 0; j < 4; j++)
                        rs += fexp2(pmax[j * 128 + rl] - mn) * psum[j * 128 + rl];
                    mrun[rb][rh] = mn;
                    rsum[rb][rh] = rs;
                }
#pragma unroll
            for (int i = 0; i < 2; i++)
#pragma unroll
                for (int j = 0; j < 4; j++)
#pragma unroll
                    for (int k = 0; k < 4; k++) acc[i][j][k] = 0.f;
        }

        buf = (buf == 2) ? 0 : buf + 1;
        bufp = (bufp == 2) ? 0 : bufp + 1;
    }

    // write partial state
    if (wc == 0 && (lane & 3) == 0) {
#pragma unroll
        for (int rb = 0; rb < 2; rb++)
#pragma unroll
            for (int rh = 0; rh < 2; rh++) {
                int rl = wr * 32 + rb * 16 + rh * 8 + g;
                g_pm[(size_t)bx * 128 + rl] = mrun[rb][rh];
                g_ps[(size_t)bx * 128 + rl] = rsum[rb][rh];
            }
    }
}

// ---------------------------------------------------------------------------
// k_final: combine 4 partials -> diag; out[b][c][n0..] = X * diag
// grid B*32, 512 threads
// ---------------------------------------------------------------------------
__global__ __launch_bounds__(512) void k_final(const float* __restrict__ X,
                                               float* __restrict__ out) {
    __shared__ float sdiag[128];
    const int bx = blockIdx.x;
    const int b = bx >> 5, nt = bx & 31;
    const int n0 = nt << 7;
    const int tid = threadIdx.x;

    if (tid < 128) {
        float pm[4];
        float M = -3.0e38f;
#pragma unroll
        for (int q = 0; q < 4; q++) {
            pm[q] = g_pm[((size_t)bx * 4 + q) * 128 + tid];
            M = fmaxf(M, pm[q]);
        }
        float S = 0.f;
#pragma unroll
        for (int q = 0; q < 4; q++)
            S += g_ps[((size_t)bx * 4 + q) * 128 + tid] * fexp2(pm[q] - M);
        sdiag[tid] = fexp2(g_dlog[(size_t)bx * 128 + tid] - M) / S *
                     (1.0f / (1.0f + 1e-8f));
    }
    __syncthreads();

    const float* Xb = X + (size_t)b * CC * NN;
    float* Ob = out + (size_t)b * CC * NN;
#pragma unroll 4
    for (int t = 0; t < 16; t++) {
        int f = tid + t * 512;
        int row = f >> 5;
        int c4 = (f & 31) << 2;
        float4 v = *(const float4*)&Xb[(size_t)row * NN + n0 + c4];
        float4 dv = *(const float4*)&sdiag[c4];
        v.x *= dv.x; v.y *= dv.y; v.z *= dv.z; v.w *= dv.w;
        *(float4*)&Ob[(size_t)row * NN + n0 + c4] = v;
    }
}

// ---------------------------------------------------------------------------
extern "C" void kernel_launch(void* const* d_in, const int* in_sizes, int n_in,
                              void* d_out, int out_size) {
    const float* X  = (const float*)d_in[0];
    const float* Wq = (const float*)d_in[1];
    const float* Wk = (const float*)d_in[2];
    float* out = (float*)d_out;

    cudaFuncSetAttribute(k_Zt, cudaFuncAttributeMaxDynamicSharedMemorySize, 131072);
    cudaFuncSetAttribute(k_part, cudaFuncAttributeMaxDynamicSharedMemorySize, SM_TOTAL);

    k_prepA<<<dim3(8, 32), dim3(32, 8)>>>(Wq, Wk);
    k_prep<<<dim3(NN / 32, CC / 32, BB), dim3(32, 8)>>>(X);
    k_Zt<<<dim3(32, 2, BB), 256, 131072>>>();
    k_part<<<BB * 32 * 4, 512, SM_TOTAL>>>();
    k_final<<<BB * 32, 512>>>(X, out);
}